// round 10
// baseline (speedup 1.0000x reference)
#include <cuda_runtime.h>
#include <math_constants.h>

#define NN  1024
#define VV  32000
#define BB  16
#define TT  128
#define GG  128            // CTAs in forward kernel (all co-resident)
#define RR  (NN/GG)        // 8 rows of E_T per CTA
#define TPB 288            // 8 matvec warps + 1 sync/fetch warp
#define AST 36             // alpha partial row stride (bank-conflict pad)

typedef unsigned long long ull;

// ---------------- device scratch (static; no runtime alloc) ----------------
__device__ unsigned short d_ETh[NN*NN];       // bf16 exp(log_T' - rowmax), 2 MB
__device__ float          d_rowmax[NN];
__device__ float          d_rowlse[NN];
__device__ float          d_collse[NN];
__device__ float          d_piadj[NN];        // log_pi - rowmax
__device__ float          d_emitg[TT*NN*BB];  // emit - rowlse + rowmax, [t][m][b]
__device__ unsigned short d_eag[2][BB*NN];    // bf16 exp(alpha - shift), ping-pong
__device__ float          d_easum[TT*BB];     // sum_n ea per (t,b)
__device__ float          d_shift[TT*BB];     // shift used per (t,b)
__device__ unsigned       d_barcnt[2];        // per-set barrier counters

// ---------------- helpers ----------------
__device__ __forceinline__ ull ffma2(ull a, ull b, ull c) {
    ull d;
    asm("fma.rn.f32x2 %0, %1, %2, %3;" : "=l"(d) : "l"(a), "l"(b), "l"(c));
    return d;
}
__device__ __forceinline__ ull bf2f32x2(unsigned u) {
    unsigned lo = u << 16, hi = u & 0xffff0000u;
    ull p;
    asm("mov.b64 %0, {%1,%2};" : "=l"(p) : "r"(lo), "r"(hi));
    return p;
}
__device__ __forceinline__ void cp_async16(unsigned dst_smem, const void* src) {
    asm volatile("cp.async.cg.shared.global [%0], [%1], 16;"
                 :: "r"(dst_smem), "l"(src));
}
__device__ __forceinline__ unsigned bf16x2pack(float lo, float hi) {
    unsigned r;
    asm("cvt.rn.bf16x2.f32 %0, %1, %2;" : "=r"(r) : "f"(hi), "f"(lo));
    return r;
}

// ---------------- prep kernel 1: rowlse (blocks 0..1023) + collse (1024..1055)
__global__ void k_pre1(const float* __restrict__ emis,
                       const float* __restrict__ trans) {
    if (blockIdx.x < NN) {
        int n = blockIdx.x;
        const float* row = emis + (size_t)n * VV;
        float mx = -CUDART_INF_F, s = 0.f;
        for (int i = threadIdx.x; i < VV; i += 256) {
            float v = row[i];
            if (v > mx) { s = s * __expf(mx - v) + 1.f; mx = v; }
            else        { s += __expf(v - mx); }
        }
        __shared__ float smx[256], ss[256];
        smx[threadIdx.x] = mx; ss[threadIdx.x] = s;
        __syncthreads();
        for (int off = 128; off; off >>= 1) {
            if (threadIdx.x < off) {
                float m1 = smx[threadIdx.x], s1 = ss[threadIdx.x];
                float m2 = smx[threadIdx.x + off], s2 = ss[threadIdx.x + off];
                float m = fmaxf(m1, m2);
                ss[threadIdx.x]  = s1 * __expf(m1 - m) + s2 * __expf(m2 - m);
                smx[threadIdx.x] = m;
            }
            __syncthreads();
        }
        if (threadIdx.x == 0) d_rowlse[n] = smx[0] + __logf(ss[0]);
    } else {
        int tx = threadIdx.x & 31, ty = threadIdx.x >> 5;   // 32 x 8
        int col = (blockIdx.x - NN) * 32 + tx;
        float mx = -CUDART_INF_F, s = 0.f;
        for (int m = ty; m < NN; m += 8) {
            float v = trans[m * NN + col];
            if (v > mx) { s = s * __expf(mx - v) + 1.f; mx = v; }
            else        { s += __expf(v - mx); }
        }
        __shared__ float cmx[8][32], cs[8][32];
        cmx[ty][tx] = mx; cs[ty][tx] = s;
        __syncthreads();
        if (ty == 0) {
            float m1 = mx, s1 = s;
            for (int j = 1; j < 8; j++) {
                float m2 = cmx[j][tx], s2 = cs[j][tx];
                float m = fmaxf(m1, m2);
                s1 = s1 * __expf(m1 - m) + s2 * __expf(m2 - m);
                m1 = m;
            }
            d_collse[col] = m1 + __logf(s1);
        }
    }
}

// ---------------- prep kernel 2: rowmax + bf16 E_T ----------------
__global__ void k_prepT(const float* __restrict__ trans) {
    int m = blockIdx.x;
    const float* rowp = trans + (size_t)m * NN;
    float mx = -CUDART_INF_F;
    for (int n = threadIdx.x; n < NN; n += 256)
        mx = fmaxf(mx, rowp[n] - d_collse[n]);
    __shared__ float smx[256];
    smx[threadIdx.x] = mx; __syncthreads();
    for (int off = 128; off; off >>= 1) {
        if (threadIdx.x < off)
            smx[threadIdx.x] = fmaxf(smx[threadIdx.x], smx[threadIdx.x + off]);
        __syncthreads();
    }
    float rm = smx[0];
    if (threadIdx.x == 0) d_rowmax[m] = rm;
    for (int n = threadIdx.x; n < NN; n += 256) {
        float e = __expf(rowp[n] - d_collse[n] - rm);
        unsigned r;
        asm("cvt.rn.bf16x2.f32 %0, %1, %2;" : "=r"(r) : "f"(0.f), "f"(e));
        d_ETh[m * NN + n] = (unsigned short)(r & 0xffffu);
    }
}

// ---------------- prep kernel 3: gather (blocks 0..127) + init (128..143) ---
__global__ void k_pre3(const float* __restrict__ emis,
                       const int* __restrict__ x,
                       const float* __restrict__ pri) {
    if (blockIdx.x < TT) {
        int t = blockIdx.x;
        __shared__ int tok[BB];
        if (threadIdx.x < BB) tok[threadIdx.x] = x[threadIdx.x * TT + t];
        __syncthreads();
        float* dst = d_emitg + (size_t)t * NN * BB;
        for (int i = threadIdx.x; i < NN * BB; i += 256) {
            int m = i >> 4, b = i & 15;
            dst[i] = __ldg(&emis[(size_t)m * VV + tok[b]])
                     - d_rowlse[m] + d_rowmax[m];
        }
    } else {
        int j = blockIdx.x - TT;   // 0..15
        if (threadIdx.x < 128) d_easum[j * 128 + threadIdx.x] = 0.f;
        if (j == 0) {
            if (threadIdx.x < 2) d_barcnt[threadIdx.x] = 0u;
            float mx = -CUDART_INF_F, s = 0.f;
            for (int i = threadIdx.x; i < NN; i += 256) {
                float v = pri[i];
                if (v > mx) { s = s * __expf(mx - v) + 1.f; mx = v; }
                else        { s += __expf(v - mx); }
            }
            __shared__ float smx[256], ss[256];
            smx[threadIdx.x] = mx; ss[threadIdx.x] = s;
            __syncthreads();
            for (int off = 128; off; off >>= 1) {
                if (threadIdx.x < off) {
                    float m1 = smx[threadIdx.x], s1 = ss[threadIdx.x];
                    float m2 = smx[threadIdx.x + off], s2 = ss[threadIdx.x + off];
                    float m = fmaxf(m1, m2);
                    ss[threadIdx.x]  = s1 * __expf(m1 - m) + s2 * __expf(m2 - m);
                    smx[threadIdx.x] = m;
                }
                __syncthreads();
            }
            __shared__ float lp;
            if (threadIdx.x == 0) lp = smx[0] + __logf(ss[0]);
            __syncthreads();
            for (int m = threadIdx.x; m < NN; m += 256)
                d_piadj[m] = pri[m] - lp - d_rowmax[m];
        }
    }
}

// ---------------- persistent forward: 2-set interleaved pipeline ------------
// smem: E bf16 16KB | ea smem 4 x 16KB (set x parity) | alpha 64*AST floats
#define EA_OFF   (RR*NN*2)
#define AL_OFF   (EA_OFF + 4*16384)
#define FWD_SMEM (AL_OFF + 64*AST*4)

__global__ void __launch_bounds__(TPB, 1)
k_forward(const int* __restrict__ len, float* __restrict__ out) {
    extern __shared__ char sh[];
    char*  E_shb   = sh;                       // [RR][NN] bf16
    char*  ea_base = sh + EA_OFF;              // [set][parity][8*NN] bf16
    float* alpha   = (float*)(sh + AL_OFF);    // [64][AST] partials
    __shared__ float sA[2][8], sB[2][8], wsum[2][8];

    const int g = blockIdx.x, tid = threadIdx.x;
    const int w = tid >> 5, lane = tid & 31;
    const bool isW8 = (w == 8);
    const int mt = w & 1, nq = w >> 1;         // matvec ids (valid w<8)
    const unsigned smem_u = (unsigned)__cvta_generic_to_shared(sh);

    // stage E_T slice once
    {
        const uint4* src = (const uint4*)(d_ETh + (size_t)g * RR * NN);
        uint4* dst = (uint4*)E_shb;
        for (int i = tid; i < RR * NN * 2 / 16; i += TPB) dst[i] = src[i];
    }
    if (tid < 16) { sA[tid >> 3][tid & 7] = 0.f; sB[tid >> 3][tid & 7] = 0.f; }
    __syncthreads();

    // warp8 per-set predictor state (lanes 0-7 meaningful)
    float sPrev0 = 0.f, lseP0 = 0.f, sPrev1 = 0.f, lseP1 = 0.f;

    for (int t = 0; t < TT; t++) {
#pragma unroll
        for (int s = 0; s < 2; s++) {
            if (isW8) {
                // all fetch groups needed this phase are complete
                asm volatile("cp.async.wait_group 0;" ::: "memory");
                asm volatile("bar.arrive %0, %1;" :: "r"(4 + s), "r"(TPB));

                // shift(t) for set s from exact lse(t-1)
                float sPrev = s ? sPrev1 : sPrev0;
                float lseP  = s ? lseP1  : lseP0;
                if (lane < 8) {
                    float sh_t = 0.f;
                    if (t >= 1) {
                        float es = __ldcg(&d_easum[(t - 1) * BB + s * 8 + lane]);
                        float lse = sPrev + __logf(es);
                        float d = (t >= 2)
                            ? fminf(20.f, fmaxf(-40.f, lse - lseP)) : 0.f;
                        sh_t = lse + d;
                        lseP = lse;
                    }
                    sA[s][lane] = sPrev;
                    sB[s][lane] = sh_t;
                    sPrev = sh_t;
                    if (g == 0) d_shift[t * BB + s * 8 + lane] = sh_t;
                }
                if (s) { sPrev1 = sPrev; lseP1 = lseP; }
                else   { sPrev0 = sPrev; lseP0 = lseP; }

                // spin the other/own counter and prefetch next ea slab
                bool dofetch; int spin_set, tgt, src_par, dst_buf, goff;
                if (s == 0) {
                    dofetch = (t >= 1); spin_set = 1; tgt = t * GG;
                    src_par = (t - 1) & 1; dst_buf = 2 + ((t - 1) & 1);
                    goff = 8 * NN * 2;
                } else {
                    dofetch = (t <= TT - 2); spin_set = 0; tgt = (t + 1) * GG;
                    src_par = t & 1; dst_buf = 0 + (t & 1);
                    goff = 0;
                }
                if (dofetch) {
                    if (lane == 0) {
                        unsigned v;
                        do {
                            asm volatile("ld.acquire.gpu.u32 %0, [%1];"
                                         : "=r"(v) : "l"(&d_barcnt[spin_set]));
                        } while (v < (unsigned)tgt);
                    }
                    __syncwarp();
                    unsigned dst = smem_u + EA_OFF +
                                   (unsigned)dst_buf * 16384u + lane * 16;
                    const char* srcp =
                        (const char*)d_eag[src_par] + goff + lane * 16;
#pragma unroll
                    for (int i = 0; i < 32; i++)
                        cp_async16(dst + i * 512, srcp + i * 512);
                    asm volatile("cp.async.commit_group;" ::: "memory");
                }
            } else {
                asm volatile("bar.sync %0, %1;" :: "r"(4 + s), "r"(TPB));
            }

            // emit prefetch (finalize threads)
            float em = 0.f, pa = 0.f;
            if (tid < 64) {
                int m_f = g * RR + (tid >> 3);
                em = __ldcg(&d_emitg[((size_t)t * NN + m_f) * BB
                                     + s * 8 + (tid & 7)]);
                if (t == 0) pa = __ldcg(&d_piadj[m_f]);
            }

            // -------- matvec (8 warps, full ea slab in smem) --------
            if (!isW8 && t > 0) {
                const char* ea_rd = ea_base + ((s * 2 + ((t - 1) & 1)) << 14);
                const int n0 = nq * 256 + lane * 8;
                const char* Eb = E_shb + ((mt * 4) * NN + n0) * 2;
                const char* Ab = ea_rd + n0 * 2;
                uint4 ev[4];
#pragma unroll
                for (int j = 0; j < 4; j++)
                    ev[j] = *(const uint4*)(Eb + j * NN * 2);
                ull e[4][4];
#pragma unroll
                for (int j = 0; j < 4; j++) {
                    e[j][0] = bf2f32x2(ev[j].x); e[j][1] = bf2f32x2(ev[j].y);
                    e[j][2] = bf2f32x2(ev[j].z); e[j][3] = bf2f32x2(ev[j].w);
                }
                ull acc[4][8];
#pragma unroll
                for (int j = 0; j < 4; j++)
#pragma unroll
                    for (int k = 0; k < 8; k++) acc[j][k] = 0ull;
#pragma unroll
                for (int k = 0; k < 8; k++) {
                    uint4 av = *(const uint4*)(Ab + k * NN * 2);
                    ull a0 = bf2f32x2(av.x), a1 = bf2f32x2(av.y);
                    ull a2 = bf2f32x2(av.z), a3 = bf2f32x2(av.w);
#pragma unroll
                    for (int j = 0; j < 4; j++) {
                        acc[j][k] = ffma2(e[j][0], a0, acc[j][k]);
                        acc[j][k] = ffma2(e[j][1], a1, acc[j][k]);
                        acc[j][k] = ffma2(e[j][2], a2, acc[j][k]);
                        acc[j][k] = ffma2(e[j][3], a3, acc[j][k]);
                    }
                }
                // 2-level reduce; lanes 0-7 hold 8 partial groups
#pragma unroll
                for (int j = 0; j < 4; j++)
#pragma unroll
                    for (int k = 0; k < 8; k++) {
                        float2 f = *(float2*)&acc[j][k];
                        float r = f.x + f.y;
                        r += __shfl_xor_sync(0xffffffffu, r, 16);
                        r += __shfl_xor_sync(0xffffffffu, r, 8);
                        if (lane < 8)
                            alpha[((mt * 4 + j) * 8 + k) * AST
                                  + nq * 8 + lane] = r;
                    }
            }
            __syncthreads();   // alpha + sA/sB visible

            // -------- finalize: alpha -> ea, pack, warp sums --------
            if (tid < 64) {
                float A;
                if (t == 0) A = em + pa;
                else {
                    const float4* p = (const float4*)(alpha + tid * AST);
                    float ssum = 0.f;
#pragma unroll
                    for (int q = 0; q < 8; q++) {
                        float4 v = p[q];
                        ssum += (v.x + v.y) + (v.z + v.w);
                    }
                    A = em + sA[s][tid & 7] + __logf(ssum);
                }
                float e = __expf(A - sB[s][tid & 7]);
                float e1 = __shfl_down_sync(0xffffffffu, e, 8);
                if (((tid >> 3) & 1) == 0) {
                    unsigned* dst = (unsigned*)((char*)d_eag[t & 1]
                        + ((s * 8 + (tid & 7)) * NN + g * RR + (tid >> 3)) * 2);
                    *dst = bf16x2pack(e, e1);
                }
                float sm = e;
                sm += __shfl_xor_sync(0xffffffffu, sm, 8);
                sm += __shfl_xor_sync(0xffffffffu, sm, 16);
                if (lane < 8) wsum[w][lane] = sm;
            }
            __syncthreads();
            if (tid < 8)
                atomicAdd(&d_easum[t * BB + s * 8 + tid],
                          wsum[0][tid] + wsum[1][tid]);
            __syncthreads();
            if (tid == 0)
                asm volatile("red.release.gpu.add.u32 [%0], 1;"
                             :: "l"(&d_barcnt[s]));
        }
    }

    // -------- final output --------
    if (g == 0) {
        if (tid == 0) {
            unsigned v;
            do { asm volatile("ld.acquire.gpu.u32 %0,[%1];"
                              : "=r"(v) : "l"(&d_barcnt[0]));
            } while (v < (unsigned)(TT * GG));
            do { asm volatile("ld.acquire.gpu.u32 %0,[%1];"
                              : "=r"(v) : "l"(&d_barcnt[1]));
            } while (v < (unsigned)(TT * GG));
        }
        __syncthreads();
        if (tid < BB) {
            int tb = len[tid] - 1;
            tb = tb < 0 ? 0 : (tb > TT - 1 ? TT - 1 : tb);
            out[tid] = __ldcg(&d_shift[tb * BB + tid]) +
                       __logf(__ldcg(&d_easum[tb * BB + tid]));
        }
    }
}

// ---------------- launch: 4 kernels; forward is launch #4 ----------------
extern "C" void kernel_launch(void* const* d_in, const int* in_sizes, int n_in,
                              void* d_out, int out_size) {
    (void)in_sizes; (void)n_in; (void)out_size;
    const float* emis  = (const float*)d_in[0];  // (N, V)
    const float* trans = (const float*)d_in[1];  // (N, N)
    const float* pri   = (const float*)d_in[2];  // (N,)
    const int*   x     = (const int*)d_in[3];    // (B, T)
    const int*   len   = (const int*)d_in[4];    // (B,)
    float*       out   = (float*)d_out;          // (B, 1)

    cudaFuncSetAttribute(k_forward, cudaFuncAttributeMaxDynamicSharedMemorySize,
                         FWD_SMEM);

    k_pre1<<<NN + NN / 32, 256>>>(emis, trans);   // rowlse + collse
    k_prepT<<<NN, 256>>>(trans);                  // rowmax + bf16 E_T
    k_pre3<<<TT + 16, 256>>>(emis, x, pri);       // gather + init
    k_forward<<<GG, TPB, FWD_SMEM>>>(len, out);   // launch #4
}